// round 1
// baseline (speedup 1.0000x reference)
#include <cuda_runtime.h>
#include <math.h>
#include <float.h>

// ---------------- problem dims ----------------
#define NB   2048
#define VV   50000
#define E1   1024
#define E2   512
#define CC   2
#define KK   200
#define EMB  300

// ---------------- scratch (single __device__ buffer, no allocs) -------------
// offsets in floats
#define OFF_EN1    0LL
#define OFF_EN2    (OFF_EN1 + (long long)NB*E1)          // 2,097,152
#define OFF_PM     (OFF_EN2 + (long long)NB*E2)
#define OFF_LV     (OFF_PM + (long long)NB*CC)
#define OFF_Z      (OFF_LV + (long long)NB*CC)
#define OFF_ZX     (OFF_Z + (long long)NB*CC)
#define OFF_ZC     (OFF_ZX + (long long)NB*CC)
#define OFF_THETA  (OFF_ZC + (long long)KK*CC)
#define OFF_MU1    (OFF_THETA + (long long)NB*KK)
#define OFF_MU2    (OFF_MU1 + (long long)KK*100)
#define OFF_MUZ    (OFF_MU2 + (long long)KK*100)
#define OFF_LOGITS (OFF_MUZ + (long long)KK*EMB)
#define OFF_BETA   (OFF_LOGITS + (long long)KK*VV)
#define OFF_SPM    (OFF_BETA + (long long)KK*VV)
#define OFF_SLV    (OFF_SPM + 4)
#define OFF_SZ     (OFF_SLV + 4)
#define OFF_ST     (OFF_SZ + 4)
#define SCRATCH_FLOATS (OFF_ST + 8)

__device__ float g_scratch[SCRATCH_FLOATS];

__device__ __forceinline__ float softplusf(float x) {
    return fmaxf(x, 0.0f) + log1pf(expf(-fabsf(x)));
}

// ---------------- generic NT GEMM: C[M,N] = act(A[M,K] @ B[N,K]^T + bias) ---
// 128x128 block tile, BK=16, 256 threads, 8x8 microtile.
template<bool SP, bool HB>
__global__ void __launch_bounds__(256)
gemm_nt_kernel(const float* __restrict__ A, const float* __restrict__ B,
               const float* __restrict__ bias, float* __restrict__ C,
               int M, int N, int K)
{
    __shared__ float As[16][132];
    __shared__ float Bs[16][132];
    const int tid = threadIdx.x;
    const int m0 = blockIdx.y * 128;
    const int n0 = blockIdx.x * 128;
    const int tx = tid & 15;
    const int ty = tid >> 4;

    float acc[8][8];
#pragma unroll
    for (int i = 0; i < 8; i++)
#pragma unroll
        for (int j = 0; j < 8; j++) acc[i][j] = 0.0f;

    for (int k0 = 0; k0 < K; k0 += 16) {
#pragma unroll
        for (int l = 0; l < 2; l++) {
            int u   = tid + l * 256;
            int row = u >> 2;
            int kq  = (u & 3) * 4;
            int gk  = k0 + kq;
            // A tile
            {
                int gm = m0 + row;
                float4 v = make_float4(0.f, 0.f, 0.f, 0.f);
                if (gm < M) {
                    if (gk + 3 < K) {
                        v = *reinterpret_cast<const float4*>(A + (size_t)gm * K + gk);
                    } else {
                        const float* p = A + (size_t)gm * K;
                        if (gk + 0 < K) v.x = p[gk + 0];
                        if (gk + 1 < K) v.y = p[gk + 1];
                        if (gk + 2 < K) v.z = p[gk + 2];
                        if (gk + 3 < K) v.w = p[gk + 3];
                    }
                }
                As[kq + 0][row] = v.x; As[kq + 1][row] = v.y;
                As[kq + 2][row] = v.z; As[kq + 3][row] = v.w;
            }
            // B tile
            {
                int gn = n0 + row;
                float4 v = make_float4(0.f, 0.f, 0.f, 0.f);
                if (gn < N) {
                    if (gk + 3 < K) {
                        v = *reinterpret_cast<const float4*>(B + (size_t)gn * K + gk);
                    } else {
                        const float* p = B + (size_t)gn * K;
                        if (gk + 0 < K) v.x = p[gk + 0];
                        if (gk + 1 < K) v.y = p[gk + 1];
                        if (gk + 2 < K) v.z = p[gk + 2];
                        if (gk + 3 < K) v.w = p[gk + 3];
                    }
                }
                Bs[kq + 0][row] = v.x; Bs[kq + 1][row] = v.y;
                Bs[kq + 2][row] = v.z; Bs[kq + 3][row] = v.w;
            }
        }
        __syncthreads();
#pragma unroll
        for (int kk = 0; kk < 16; kk++) {
            float a[8], b[8];
            *reinterpret_cast<float4*>(&a[0]) = *reinterpret_cast<const float4*>(&As[kk][ty * 8]);
            *reinterpret_cast<float4*>(&a[4]) = *reinterpret_cast<const float4*>(&As[kk][ty * 8 + 4]);
            *reinterpret_cast<float4*>(&b[0]) = *reinterpret_cast<const float4*>(&Bs[kk][tx * 8]);
            *reinterpret_cast<float4*>(&b[4]) = *reinterpret_cast<const float4*>(&Bs[kk][tx * 8 + 4]);
#pragma unroll
            for (int i = 0; i < 8; i++)
#pragma unroll
                for (int j = 0; j < 8; j++)
                    acc[i][j] += a[i] * b[j];
        }
        __syncthreads();
    }

#pragma unroll
    for (int i = 0; i < 8; i++) {
        int gm = m0 + ty * 8 + i;
        if (gm >= M) continue;
#pragma unroll
        for (int j = 0; j < 8; j++) {
            int gn = n0 + tx * 8 + j;
            if (gn >= N) continue;
            float v = acc[i][j];
            if (HB) v += bias[gn];
            if (SP) v = softplusf(v);
            C[(size_t)gm * N + gn] = v;
        }
    }
}

// ---------------- NN GEMM: C[M,N] = A[M,K] @ B[K,N] (K % 8 == 0) ------------
__global__ void __launch_bounds__(256)
gemm_nn_kernel(const float* __restrict__ A, const float* __restrict__ B,
               float* __restrict__ C, int M, int N, int K)
{
    __shared__ float As[8][132];
    __shared__ float Bs[8][132];
    const int tid = threadIdx.x;
    const int m0 = blockIdx.y * 128;
    const int n0 = blockIdx.x * 128;
    const int tx = tid & 15;
    const int ty = tid >> 4;

    float acc[8][8];
#pragma unroll
    for (int i = 0; i < 8; i++)
#pragma unroll
        for (int j = 0; j < 8; j++) acc[i][j] = 0.0f;

    const int arow = tid >> 1;
    const int akq  = (tid & 1) * 4;
    const int bkk  = tid >> 5;
    const int bnc  = (tid & 31) * 4;

    for (int k0 = 0; k0 < K; k0 += 8) {
        // A: 128 rows x 8 k
        {
            int gm = m0 + arow;
            float4 v = make_float4(0.f, 0.f, 0.f, 0.f);
            if (gm < M)
                v = *reinterpret_cast<const float4*>(A + (size_t)gm * K + k0 + akq);
            As[akq + 0][arow] = v.x; As[akq + 1][arow] = v.y;
            As[akq + 2][arow] = v.z; As[akq + 3][arow] = v.w;
        }
        // B: 8 k x 128 n
        {
            int gn = n0 + bnc;
            const float* p = B + (size_t)(k0 + bkk) * N;
            float4 v = make_float4(0.f, 0.f, 0.f, 0.f);
            if (gn + 3 < N) {
                v = *reinterpret_cast<const float4*>(p + gn);
            } else {
                if (gn + 0 < N) v.x = p[gn + 0];
                if (gn + 1 < N) v.y = p[gn + 1];
                if (gn + 2 < N) v.z = p[gn + 2];
                if (gn + 3 < N) v.w = p[gn + 3];
            }
            *reinterpret_cast<float4*>(&Bs[bkk][bnc]) = v;
        }
        __syncthreads();
#pragma unroll
        for (int kk = 0; kk < 8; kk++) {
            float a[8], b[8];
            *reinterpret_cast<float4*>(&a[0]) = *reinterpret_cast<const float4*>(&As[kk][ty * 8]);
            *reinterpret_cast<float4*>(&a[4]) = *reinterpret_cast<const float4*>(&As[kk][ty * 8 + 4]);
            *reinterpret_cast<float4*>(&b[0]) = *reinterpret_cast<const float4*>(&Bs[kk][tx * 8]);
            *reinterpret_cast<float4*>(&b[4]) = *reinterpret_cast<const float4*>(&Bs[kk][tx * 8 + 4]);
#pragma unroll
            for (int i = 0; i < 8; i++)
#pragma unroll
                for (int j = 0; j < 8; j++)
                    acc[i][j] += a[i] * b[j];
        }
        __syncthreads();
    }

#pragma unroll
    for (int i = 0; i < 8; i++) {
        int gm = m0 + ty * 8 + i;
        if (gm >= M) continue;
#pragma unroll
        for (int j = 0; j < 8; j++) {
            int gn = n0 + tx * 8 + j;
            if (gn >= N) continue;
            C[(size_t)gm * N + gn] = acc[i][j];
        }
    }
}

// ---------------- mean / logvar heads: (2048,512) -> two (2048,2) -----------
__global__ void meanlogvar_kernel(const float* __restrict__ en2,
                                  const float* __restrict__ mW, const float* __restrict__ mb,
                                  const float* __restrict__ lW, const float* __restrict__ lb,
                                  float* __restrict__ pm, float* __restrict__ lv)
{
    int t = blockIdx.x * blockDim.x + threadIdx.x;
    if (t >= NB * 4) return;
    int n = t >> 2, j = t & 3;
    const float* w = (j < 2) ? (mW + j * E2) : (lW + (j - 2) * E2);
    const float* x = en2 + (size_t)n * E2;
    float s = 0.f;
    for (int i = 0; i < E2; i += 4) {
        float4 xa = *reinterpret_cast<const float4*>(x + i);
        float4 wa = *reinterpret_cast<const float4*>(w + i);
        s += xa.x * wa.x + xa.y * wa.y + xa.z * wa.z + xa.w * wa.w;
    }
    if (j < 2) pm[n * 2 + j] = s + mb[j];
    else       lv[n * 2 + (j - 2)] = s + lb[j - 2];
}

// ---------------- column stats of (R x 2): out[c]=mean, out[2+c]=biased var -
__global__ void colstats_kernel(const float* __restrict__ X, int R, float* __restrict__ out)
{
    __shared__ float ss[256], s2[256];
    int c = blockIdx.x, tid = threadIdx.x;
    float s = 0.f, q = 0.f;
    for (int r = tid; r < R; r += 256) {
        float x = X[r * 2 + c];
        s += x; q += x * x;
    }
    ss[tid] = s; s2[tid] = q;
    __syncthreads();
    for (int st = 128; st > 0; st >>= 1) {
        if (tid < st) { ss[tid] += ss[tid + st]; s2[tid] += s2[tid + st]; }
        __syncthreads();
    }
    if (tid == 0) {
        float m = ss[0] / R;
        out[c] = m;
        out[2 + c] = s2[0] / R - m * m;
    }
}

// ---------------- z = BN(pm) + sqrt(exp(BN(lv))) * eps ----------------------
__global__ void z_kernel(const float* __restrict__ pm, const float* __restrict__ lv,
                         const float* __restrict__ spm, const float* __restrict__ slv,
                         const float* __restrict__ gm, const float* __restrict__ bm,
                         const float* __restrict__ gl, const float* __restrict__ bl,
                         const float* __restrict__ eps,
                         float* __restrict__ gz, float* __restrict__ outz)
{
    int idx = blockIdx.x * 256 + threadIdx.x;
    if (idx >= NB * CC) return;
    int c = idx & 1;
    float pmb = gm[c] * (pm[idx] - spm[c]) * rsqrtf(spm[2 + c] + 1e-5f) + bm[c];
    float lvb = gl[c] * (lv[idx] - slv[c]) * rsqrtf(slv[2 + c] + 1e-5f) + bl[c];
    float z = pmb + sqrtf(expf(lvb)) * eps[idx];
    gz[idx] = z;
    outz[idx] = z;
}

// ---------------- generic BN apply on (R x 2) flat ---------------------------
__global__ void bn_apply_kernel(const float* __restrict__ X, const float* __restrict__ stats,
                                const float* __restrict__ g, const float* __restrict__ b,
                                int total, float* __restrict__ o1, float* __restrict__ o2)
{
    int idx = blockIdx.x * 256 + threadIdx.x;
    if (idx >= total) return;
    int c = idx & 1;
    float y = g[c] * (X[idx] - stats[c]) * rsqrtf(stats[2 + c] + 1e-5f) + b[c];
    o1[idx] = y;
    o2[idx] = y;
}

// ---------------- theta = softmax_k(-0.5 * ||zx_n - zc_k||^2) ---------------
__global__ void theta_kernel(const float* __restrict__ zx, const float* __restrict__ zc,
                             float* __restrict__ gtheta, float* __restrict__ otheta)
{
    __shared__ float sz[KK * 2];
    __shared__ float red[256];
    int n = blockIdx.x, tid = threadIdx.x;
    for (int i = tid; i < KK * 2; i += 256) sz[i] = zc[i];
    __syncthreads();
    float x0 = zx[n * 2], x1 = zx[n * 2 + 1];
    float l = -FLT_MAX;
    if (tid < KK) {
        float dx = x0 - sz[tid * 2];
        float dy = x1 - sz[tid * 2 + 1];
        l = -0.5f * (dx * dx + dy * dy);
    }
    red[tid] = l;
    __syncthreads();
    for (int st = 128; st > 0; st >>= 1) {
        if (tid < st) red[tid] = fmaxf(red[tid], red[tid + st]);
        __syncthreads();
    }
    float mx = red[0];
    __syncthreads();
    float e = (tid < KK) ? expf(l - mx) : 0.f;
    red[tid] = e;
    __syncthreads();
    for (int st = 128; st > 0; st >>= 1) {
        if (tid < st) red[tid] += red[tid + st];
        __syncthreads();
    }
    float inv = 1.f / red[0];
    if (tid < KK) {
        float th = e * inv;
        gtheta[(size_t)n * KK + tid] = th;
        otheta[(size_t)n * KK + tid] = th;
    }
}

// ---------------- decoder MLP ------------------------------------------------
__global__ void mu1_kernel(const float* __restrict__ zc, const float* __restrict__ W,
                           const float* __restrict__ b, float* __restrict__ out)
{
    int t = blockIdx.x * 256 + threadIdx.x;
    if (t >= KK * 100) return;
    int k = t / 100, j = t % 100;
    float v = zc[k * 2] * W[j * 2] + zc[k * 2 + 1] * W[j * 2 + 1] + b[j];
    out[t] = softplusf(v);
}

__global__ void mu2_kernel(const float* __restrict__ mu1, const float* __restrict__ W,
                           const float* __restrict__ b, float* __restrict__ out)
{
    __shared__ float row[100];
    int k = blockIdx.x, tid = threadIdx.x;
    if (tid < 100) row[tid] = mu1[k * 100 + tid];
    __syncthreads();
    if (tid < 100) {
        const float* w = W + tid * 100;
        float s = b[tid];
        for (int i = 0; i < 100; i++) s += row[i] * w[i];
        out[k * 100 + tid] = softplusf(s);
    }
}

__global__ void muz_kernel(const float* __restrict__ mu2, const float* __restrict__ W,
                           const float* __restrict__ b, float* __restrict__ out)
{
    __shared__ float row[100];
    int k = blockIdx.x, tid = threadIdx.x;
    if (tid < 100) row[tid] = mu2[k * 100 + tid];
    __syncthreads();
    for (int j = tid; j < EMB; j += 128) {
        const float* w = W + j * 100;
        float s = b[j];
        for (int i = 0; i < 100; i++) s += row[i] * w[i];
        out[k * EMB + j] = s;
    }
}

// ---------------- per-topic BN over V + softmax over V -> beta ---------------
__global__ void __launch_bounds__(1024)
beta_kernel(const float* __restrict__ logits, const float* __restrict__ bbias,
            const float* __restrict__ gdec, const float* __restrict__ bdec,
            float* __restrict__ beta)
{
    __shared__ float red[1024];
    __shared__ float red2[1024];
    const int k = blockIdx.x, tid = threadIdx.x;
    const float* row = logits + (size_t)k * VV;
    const float* bb  = bbias + (size_t)k * VV;

    float s = 0.f, q = 0.f;
    for (int v = tid; v < VV; v += 1024) { float x = row[v]; s += x; q += x * x; }
    red[tid] = s; red2[tid] = q;
    __syncthreads();
    for (int st = 512; st > 0; st >>= 1) {
        if (tid < st) { red[tid] += red[tid + st]; red2[tid] += red2[tid + st]; }
        __syncthreads();
    }
    float mean = red[0] / VV;
    float var  = red2[0] / VV - mean * mean;
    float scale = gdec[k] * rsqrtf(var + 1e-5f);
    float shift = bdec[k] - mean * scale;
    __syncthreads();

    float mx = -FLT_MAX;
    for (int v = tid; v < VV; v += 1024) {
        float y = row[v] * scale + shift + bb[v];
        mx = fmaxf(mx, y);
    }
    red[tid] = mx;
    __syncthreads();
    for (int st = 512; st > 0; st >>= 1) {
        if (tid < st) red[tid] = fmaxf(red[tid], red[tid + st]);
        __syncthreads();
    }
    mx = red[0];
    __syncthreads();

    float se = 0.f;
    for (int v = tid; v < VV; v += 1024) {
        float y = row[v] * scale + shift + bb[v];
        se += expf(y - mx);
    }
    red[tid] = se;
    __syncthreads();
    for (int st = 512; st > 0; st >>= 1) {
        if (tid < st) red[tid] += red[tid + st];
        __syncthreads();
    }
    float inv = 1.f / red[0];

    for (int v = tid; v < VV; v += 1024) {
        float y = row[v] * scale + shift + bb[v];
        beta[(size_t)k * VV + v] = expf(y - mx) * inv;
    }
}

// ---------------- launch -----------------------------------------------------
extern "C" void kernel_launch(void* const* d_in, const int* in_sizes, int n_in,
                              void* d_out, int out_size)
{
    const float* input_   = (const float*)d_in[0];
    const float* eps      = (const float*)d_in[2];
    const float* en1_W    = (const float*)d_in[3];
    const float* en1_b    = (const float*)d_in[4];
    const float* en2_W    = (const float*)d_in[5];
    const float* en2_b    = (const float*)d_in[6];
    const float* mean_W   = (const float*)d_in[7];
    const float* mean_b   = (const float*)d_in[8];
    const float* logvar_W = (const float*)d_in[9];
    const float* logvar_b = (const float*)d_in[10];
    const float* mu1_W    = (const float*)d_in[11];
    const float* mu1_b    = (const float*)d_in[12];
    const float* mu2_W    = (const float*)d_in[13];
    const float* mu2_b    = (const float*)d_in[14];
    const float* mu_W     = (const float*)d_in[15];
    const float* mu_b     = (const float*)d_in[16];
    const float* topics   = (const float*)d_in[17];
    const float* bbias    = (const float*)d_in[18];
    const float* emb      = (const float*)d_in[19];
    const float* g_mean   = (const float*)d_in[20];
    const float* b_mean   = (const float*)d_in[21];
    const float* g_logvar = (const float*)d_in[22];
    const float* b_logvar = (const float*)d_in[23];
    const float* g_x      = (const float*)d_in[24];
    const float* b_x      = (const float*)d_in[25];
    const float* g_phi    = (const float*)d_in[26];
    const float* b_phi    = (const float*)d_in[27];
    const float* g_dec    = (const float*)d_in[28];
    const float* b_dec    = (const float*)d_in[29];

    float* out = (float*)d_out;
    float* out_z     = out;
    float* out_recon = out + (long long)NB * CC;
    float* out_zx    = out_recon + (long long)NB * VV;
    float* out_zc    = out_zx + (long long)NB * CC;
    float* out_theta = out_zc + (long long)KK * CC;

    void* sp = nullptr;
    cudaGetSymbolAddress(&sp, g_scratch);
    float* S = (float*)sp;
    float* s_en1    = S + OFF_EN1;
    float* s_en2    = S + OFF_EN2;
    float* s_pm     = S + OFF_PM;
    float* s_lv     = S + OFF_LV;
    float* s_z      = S + OFF_Z;
    float* s_zx     = S + OFF_ZX;
    float* s_zc     = S + OFF_ZC;
    float* s_theta  = S + OFF_THETA;
    float* s_mu1    = S + OFF_MU1;
    float* s_mu2    = S + OFF_MU2;
    float* s_muz    = S + OFF_MUZ;
    float* s_logits = S + OFF_LOGITS;
    float* s_beta   = S + OFF_BETA;
    float* st_pm    = S + OFF_SPM;
    float* st_lv    = S + OFF_SLV;
    float* st_z     = S + OFF_SZ;
    float* st_t     = S + OFF_ST;

    // 1) en1 = softplus(input @ en1_W^T + b)   [2048 x 1024], K=50000
    gemm_nt_kernel<true, true><<<dim3(E1 / 128, NB / 128), 256>>>(
        input_, en1_W, en1_b, s_en1, NB, E1, VV);

    // 2) en2 = softplus(en1 @ en2_W^T + b)     [2048 x 512], K=1024
    gemm_nt_kernel<true, true><<<dim3(E2 / 128, NB / 128), 256>>>(
        s_en1, en2_W, en2_b, s_en2, NB, E2, E1);

    // 3) posterior mean / logvar heads
    meanlogvar_kernel<<<(NB * 4 + 255) / 256, 256>>>(
        s_en2, mean_W, mean_b, logvar_W, logvar_b, s_pm, s_lv);

    // 4) BN stats + z
    colstats_kernel<<<2, 256>>>(s_pm, NB, st_pm);
    colstats_kernel<<<2, 256>>>(s_lv, NB, st_lv);
    z_kernel<<<(NB * CC + 255) / 256, 256>>>(
        s_pm, s_lv, st_pm, st_lv, g_mean, b_mean, g_logvar, b_logvar, eps, s_z, out_z);

    // 5) zx = BN(z), zc = BN(topics)
    colstats_kernel<<<2, 256>>>(s_z, NB, st_z);
    bn_apply_kernel<<<(NB * CC + 255) / 256, 256>>>(s_z, st_z, g_x, b_x, NB * CC, s_zx, out_zx);
    colstats_kernel<<<2, 256>>>(topics, KK, st_t);
    bn_apply_kernel<<<(KK * CC + 255) / 256, 256>>>(topics, st_t, g_phi, b_phi, KK * CC, s_zc, out_zc);

    // 6) theta
    theta_kernel<<<NB, 256>>>(s_zx, s_zc, s_theta, out_theta);

    // 7) decoder MLP: mu1 -> mu2 -> mu_z
    mu1_kernel<<<(KK * 100 + 255) / 256, 256>>>(s_zc, mu1_W, mu1_b, s_mu1);
    mu2_kernel<<<KK, 128>>>(s_mu1, mu2_W, mu2_b, s_mu2);
    muz_kernel<<<KK, 128>>>(s_mu2, mu_W, mu_b, s_muz);

    // 8) logits = mu_z @ emb^T   [200 x 50000], K=300
    gemm_nt_kernel<false, false><<<dim3((VV + 127) / 128, (KK + 127) / 128), 256>>>(
        s_muz, emb, nullptr, s_logits, KK, VV, EMB);

    // 9) beta = softmax_V(BN_topic(logits) + beta_bias)
    beta_kernel<<<KK, 1024>>>(s_logits, bbias, g_dec, b_dec, s_beta);

    // 10) recon_v = theta @ beta   [2048 x 50000], K=200
    gemm_nn_kernel<<<dim3((VV + 127) / 128, NB / 128), 256>>>(
        s_theta, s_beta, out_recon, NB, VV, KK);

    (void)in_sizes; (void)n_in; (void)out_size;
}

// round 2
// speedup vs baseline: 2.2484x; 2.2484x over previous
#include <cuda_runtime.h>
#include <math.h>
#include <float.h>

// ---------------- problem dims ----------------
#define NB   2048
#define VV   50000
#define E1   1024
#define E2   512
#define CC   2
#define KK   200
#define EMB  300

// ---------------- scratch ----------------------------------------------------
#define OFF_EN1    0LL
#define OFF_EN2    (OFF_EN1 + (long long)NB*E1)
#define OFF_PM     (OFF_EN2 + (long long)NB*E2)
#define OFF_LV     (OFF_PM + (long long)NB*CC)
#define OFF_Z      (OFF_LV + (long long)NB*CC)
#define OFF_ZX     (OFF_Z + (long long)NB*CC)
#define OFF_ZC     (OFF_ZX + (long long)NB*CC)
#define OFF_THETA  (OFF_ZC + (long long)KK*CC)
#define OFF_MU1    (OFF_THETA + (long long)NB*KK)
#define OFF_MU2    (OFF_MU1 + (long long)KK*100)
#define OFF_MUZ    (OFF_MU2 + (long long)KK*100)
#define OFF_LOGITS (OFF_MUZ + (long long)KK*EMB)
#define OFF_BETA   (OFF_LOGITS + (long long)KK*VV)
#define OFF_SPM    (OFF_BETA + (long long)KK*VV)
#define OFF_SLV    (OFF_SPM + 4)
#define OFF_SZ     (OFF_SLV + 4)
#define OFF_ST     (OFF_SZ + 4)
#define SCRATCH_FLOATS (OFF_ST + 8)

__device__ float g_scratch[SCRATCH_FLOATS];

__device__ __forceinline__ float softplusf(float x) {
    return fmaxf(x, 0.0f) + log1pf(expf(-fabsf(x)));
}

__device__ __forceinline__ unsigned tf32_rna(float x) {
    unsigned r;
    asm("cvt.rna.tf32.f32 %0, %1;" : "=r"(r) : "f"(x));
    return r;
}

__device__ __forceinline__ void mma_tf32(float* d,
                                         unsigned a0, unsigned a1, unsigned a2, unsigned a3,
                                         unsigned b0, unsigned b1)
{
    asm volatile(
        "mma.sync.aligned.m16n8k8.row.col.f32.tf32.tf32.f32 "
        "{%0,%1,%2,%3},{%4,%5,%6,%7},{%8,%9},{%0,%1,%2,%3};"
        : "+f"(d[0]), "+f"(d[1]), "+f"(d[2]), "+f"(d[3])
        : "r"(a0), "r"(a1), "r"(a2), "r"(a3), "r"(b0), "r"(b1));
}

// =============================================================================
// GEMM1: en1 = softplus(input[2048,50000] @ en1_W[1024,50000]^T + b)
// 3xTF32 split for ~fp32 accuracy. BM=128, BN=64, BK=16, 256 thr, warp 32x32.
// =============================================================================
__global__ void __launch_bounds__(256, 2)
gemm1_tf32x3(const float* __restrict__ A, const float* __restrict__ B,
             const float* __restrict__ bias, float* __restrict__ C)
{
    __shared__ float Ah[128][20], Al[128][20], Bh[64][20], Bl[64][20];
    const int tid = threadIdx.x;
    const int lane = tid & 31, warp = tid >> 5;
    const int gid = lane >> 2, tig = lane & 3;
    const int wm = warp >> 1, wn = warp & 1;
    const int m0 = blockIdx.y * 128;
    const int n0 = blockIdx.x * 64;

    float acc[2][4][4];
#pragma unroll
    for (int i = 0; i < 2; i++)
#pragma unroll
        for (int j = 0; j < 4; j++)
#pragma unroll
            for (int l = 0; l < 4; l++) acc[i][j][l] = 0.0f;

    for (int k0 = 0; k0 < VV; k0 += 16) {
        // load A: 512 float4 -> 2 per thread
#pragma unroll
        for (int l = 0; l < 2; l++) {
            int idx = tid + l * 256;
            int row = idx >> 2, kq = (idx & 3) * 4;
            float4 v = *reinterpret_cast<const float4*>(A + (size_t)(m0 + row) * VV + k0 + kq);
            float4 h, lo;
            h.x = __uint_as_float(tf32_rna(v.x)); lo.x = __uint_as_float(tf32_rna(v.x - h.x));
            h.y = __uint_as_float(tf32_rna(v.y)); lo.y = __uint_as_float(tf32_rna(v.y - h.y));
            h.z = __uint_as_float(tf32_rna(v.z)); lo.z = __uint_as_float(tf32_rna(v.z - h.z));
            h.w = __uint_as_float(tf32_rna(v.w)); lo.w = __uint_as_float(tf32_rna(v.w - h.w));
            *reinterpret_cast<float4*>(&Ah[row][kq]) = h;
            *reinterpret_cast<float4*>(&Al[row][kq]) = lo;
        }
        // load B: 256 float4 -> 1 per thread
        {
            int row = tid >> 2, kq = (tid & 3) * 4;
            float4 v = *reinterpret_cast<const float4*>(B + (size_t)(n0 + row) * VV + k0 + kq);
            float4 h, lo;
            h.x = __uint_as_float(tf32_rna(v.x)); lo.x = __uint_as_float(tf32_rna(v.x - h.x));
            h.y = __uint_as_float(tf32_rna(v.y)); lo.y = __uint_as_float(tf32_rna(v.y - h.y));
            h.z = __uint_as_float(tf32_rna(v.z)); lo.z = __uint_as_float(tf32_rna(v.z - h.z));
            h.w = __uint_as_float(tf32_rna(v.w)); lo.w = __uint_as_float(tf32_rna(v.w - h.w));
            *reinterpret_cast<float4*>(&Bh[row][kq]) = h;
            *reinterpret_cast<float4*>(&Bl[row][kq]) = lo;
        }
        __syncthreads();

#pragma unroll
        for (int kk = 0; kk < 16; kk += 8) {
            unsigned ah[2][4], al[2][4], bh[4][2], bl[4][2];
#pragma unroll
            for (int ms = 0; ms < 2; ms++) {
                int r = wm * 32 + ms * 16 + gid;
                ah[ms][0] = __float_as_uint(Ah[r][kk + tig]);
                ah[ms][1] = __float_as_uint(Ah[r + 8][kk + tig]);
                ah[ms][2] = __float_as_uint(Ah[r][kk + tig + 4]);
                ah[ms][3] = __float_as_uint(Ah[r + 8][kk + tig + 4]);
                al[ms][0] = __float_as_uint(Al[r][kk + tig]);
                al[ms][1] = __float_as_uint(Al[r + 8][kk + tig]);
                al[ms][2] = __float_as_uint(Al[r][kk + tig + 4]);
                al[ms][3] = __float_as_uint(Al[r + 8][kk + tig + 4]);
            }
#pragma unroll
            for (int ns = 0; ns < 4; ns++) {
                int n = wn * 32 + ns * 8 + gid;
                bh[ns][0] = __float_as_uint(Bh[n][kk + tig]);
                bh[ns][1] = __float_as_uint(Bh[n][kk + tig + 4]);
                bl[ns][0] = __float_as_uint(Bl[n][kk + tig]);
                bl[ns][1] = __float_as_uint(Bl[n][kk + tig + 4]);
            }
#pragma unroll
            for (int ms = 0; ms < 2; ms++)
#pragma unroll
                for (int ns = 0; ns < 4; ns++) {
                    mma_tf32(acc[ms][ns], ah[ms][0], ah[ms][1], ah[ms][2], ah[ms][3],
                             bh[ns][0], bh[ns][1]);
                    mma_tf32(acc[ms][ns], ah[ms][0], ah[ms][1], ah[ms][2], ah[ms][3],
                             bl[ns][0], bl[ns][1]);
                    mma_tf32(acc[ms][ns], al[ms][0], al[ms][1], al[ms][2], al[ms][3],
                             bh[ns][0], bh[ns][1]);
                }
        }
        __syncthreads();
    }

    // epilogue: bias + softplus
#pragma unroll
    for (int ms = 0; ms < 2; ms++) {
        int r0 = m0 + wm * 32 + ms * 16 + gid;
#pragma unroll
        for (int ns = 0; ns < 4; ns++) {
            int c0 = n0 + wn * 32 + ns * 8 + 2 * tig;
            float b0v = bias[c0], b1v = bias[c0 + 1];
            C[(size_t)r0 * E1 + c0]            = softplusf(acc[ms][ns][0] + b0v);
            C[(size_t)r0 * E1 + c0 + 1]        = softplusf(acc[ms][ns][1] + b1v);
            C[(size_t)(r0 + 8) * E1 + c0]      = softplusf(acc[ms][ns][2] + b0v);
            C[(size_t)(r0 + 8) * E1 + c0 + 1]  = softplusf(acc[ms][ns][3] + b1v);
        }
    }
}

// =============================================================================
// recon = theta[2048,200] @ beta[200,50000]  (NN, single-pass tf32)
// BM=128, BN=128, BK=16, 256 thr, warp tile 32x64 (4x2 warps).
// =============================================================================
__global__ void __launch_bounds__(256, 2)
recon_tf32(const float* __restrict__ A, const float* __restrict__ B,
           float* __restrict__ C)
{
    __shared__ float Ah[128][20];
    __shared__ float Bh[16][136];
    const int tid = threadIdx.x;
    const int lane = tid & 31, warp = tid >> 5;
    const int gid = lane >> 2, tig = lane & 3;
    const int wm = warp >> 1, wn = warp & 1;
    const int m0 = blockIdx.y * 128;
    const int n0 = blockIdx.x * 128;

    float acc[2][8][4];
#pragma unroll
    for (int i = 0; i < 2; i++)
#pragma unroll
        for (int j = 0; j < 8; j++)
#pragma unroll
            for (int l = 0; l < 4; l++) acc[i][j][l] = 0.0f;

    for (int k0 = 0; k0 < KK; k0 += 16) {
        // A (theta): 128 rows x 16 k
#pragma unroll
        for (int l = 0; l < 2; l++) {
            int idx = tid + l * 256;
            int row = idx >> 2, kq = (idx & 3) * 4;
            int gk = k0 + kq;
            float4 v = make_float4(0.f, 0.f, 0.f, 0.f);
            if (gk + 3 < KK)
                v = *reinterpret_cast<const float4*>(A + (size_t)(m0 + row) * KK + gk);
            Ah[row][kq + 0] = __uint_as_float(tf32_rna(v.x));
            Ah[row][kq + 1] = __uint_as_float(tf32_rna(v.y));
            Ah[row][kq + 2] = __uint_as_float(tf32_rna(v.z));
            Ah[row][kq + 3] = __uint_as_float(tf32_rna(v.w));
        }
        // B (beta): 16 k x 128 n
#pragma unroll
        for (int l = 0; l < 2; l++) {
            int idx = tid + l * 256;
            int kk = idx >> 5, nc = (idx & 31) * 4;
            int gk = k0 + kk, gn = n0 + nc;
            float4 v = make_float4(0.f, 0.f, 0.f, 0.f);
            if (gk < KK && gn + 3 < VV)
                v = *reinterpret_cast<const float4*>(B + (size_t)gk * VV + gn);
            Bh[kk][nc + 0] = __uint_as_float(tf32_rna(v.x));
            Bh[kk][nc + 1] = __uint_as_float(tf32_rna(v.y));
            Bh[kk][nc + 2] = __uint_as_float(tf32_rna(v.z));
            Bh[kk][nc + 3] = __uint_as_float(tf32_rna(v.w));
        }
        __syncthreads();

#pragma unroll
        for (int kk = 0; kk < 16; kk += 8) {
            unsigned a[2][4], b[8][2];
#pragma unroll
            for (int ms = 0; ms < 2; ms++) {
                int r = wm * 32 + ms * 16 + gid;
                a[ms][0] = __float_as_uint(Ah[r][kk + tig]);
                a[ms][1] = __float_as_uint(Ah[r + 8][kk + tig]);
                a[ms][2] = __float_as_uint(Ah[r][kk + tig + 4]);
                a[ms][3] = __float_as_uint(Ah[r + 8][kk + tig + 4]);
            }
#pragma unroll
            for (int ns = 0; ns < 8; ns++) {
                int n = wn * 64 + ns * 8 + gid;
                b[ns][0] = __float_as_uint(Bh[kk + tig][n]);
                b[ns][1] = __float_as_uint(Bh[kk + tig + 4][n]);
            }
#pragma unroll
            for (int ms = 0; ms < 2; ms++)
#pragma unroll
                for (int ns = 0; ns < 8; ns++)
                    mma_tf32(acc[ms][ns], a[ms][0], a[ms][1], a[ms][2], a[ms][3],
                             b[ns][0], b[ns][1]);
        }
        __syncthreads();
    }

#pragma unroll
    for (int ms = 0; ms < 2; ms++) {
        int r0 = m0 + wm * 32 + ms * 16 + gid;
#pragma unroll
        for (int ns = 0; ns < 8; ns++) {
            int c0 = n0 + wn * 64 + ns * 8 + 2 * tig;
            if (c0 < VV) {
                C[(size_t)r0 * VV + c0]       = acc[ms][ns][0];
                C[(size_t)(r0 + 8) * VV + c0] = acc[ms][ns][2];
            }
            if (c0 + 1 < VV) {
                C[(size_t)r0 * VV + c0 + 1]       = acc[ms][ns][1];
                C[(size_t)(r0 + 8) * VV + c0 + 1] = acc[ms][ns][3];
            }
        }
    }
}

// ---------------- fp32 NT GEMM (kept for GEMM2 + logits) --------------------
template<bool SP, bool HB>
__global__ void __launch_bounds__(256)
gemm_nt_kernel(const float* __restrict__ A, const float* __restrict__ B,
               const float* __restrict__ bias, float* __restrict__ C,
               int M, int N, int K)
{
    __shared__ float As[16][132];
    __shared__ float Bs[16][132];
    const int tid = threadIdx.x;
    const int m0 = blockIdx.y * 128;
    const int n0 = blockIdx.x * 128;
    const int tx = tid & 15;
    const int ty = tid >> 4;

    float acc[8][8];
#pragma unroll
    for (int i = 0; i < 8; i++)
#pragma unroll
        for (int j = 0; j < 8; j++) acc[i][j] = 0.0f;

    for (int k0 = 0; k0 < K; k0 += 16) {
#pragma unroll
        for (int l = 0; l < 2; l++) {
            int u   = tid + l * 256;
            int row = u >> 2;
            int kq  = (u & 3) * 4;
            int gk  = k0 + kq;
            {
                int gm = m0 + row;
                float4 v = make_float4(0.f, 0.f, 0.f, 0.f);
                if (gm < M) {
                    if (gk + 3 < K) {
                        v = *reinterpret_cast<const float4*>(A + (size_t)gm * K + gk);
                    } else {
                        const float* p = A + (size_t)gm * K;
                        if (gk + 0 < K) v.x = p[gk + 0];
                        if (gk + 1 < K) v.y = p[gk + 1];
                        if (gk + 2 < K) v.z = p[gk + 2];
                        if (gk + 3 < K) v.w = p[gk + 3];
                    }
                }
                As[kq + 0][row] = v.x; As[kq + 1][row] = v.y;
                As[kq + 2][row] = v.z; As[kq + 3][row] = v.w;
            }
            {
                int gn = n0 + row;
                float4 v = make_float4(0.f, 0.f, 0.f, 0.f);
                if (gn < N) {
                    if (gk + 3 < K) {
                        v = *reinterpret_cast<const float4*>(B + (size_t)gn * K + gk);
                    } else {
                        const float* p = B + (size_t)gn * K;
                        if (gk + 0 < K) v.x = p[gk + 0];
                        if (gk + 1 < K) v.y = p[gk + 1];
                        if (gk + 2 < K) v.z = p[gk + 2];
                        if (gk + 3 < K) v.w = p[gk + 3];
                    }
                }
                Bs[kq + 0][row] = v.x; Bs[kq + 1][row] = v.y;
                Bs[kq + 2][row] = v.z; Bs[kq + 3][row] = v.w;
            }
        }
        __syncthreads();
#pragma unroll
        for (int kk = 0; kk < 16; kk++) {
            float a[8], b[8];
            *reinterpret_cast<float4*>(&a[0]) = *reinterpret_cast<const float4*>(&As[kk][ty * 8]);
            *reinterpret_cast<float4*>(&a[4]) = *reinterpret_cast<const float4*>(&As[kk][ty * 8 + 4]);
            *reinterpret_cast<float4*>(&b[0]) = *reinterpret_cast<const float4*>(&Bs[kk][tx * 8]);
            *reinterpret_cast<float4*>(&b[4]) = *reinterpret_cast<const float4*>(&Bs[kk][tx * 8 + 4]);
#pragma unroll
            for (int i = 0; i < 8; i++)
#pragma unroll
                for (int j = 0; j < 8; j++)
                    acc[i][j] += a[i] * b[j];
        }
        __syncthreads();
    }

#pragma unroll
    for (int i = 0; i < 8; i++) {
        int gm = m0 + ty * 8 + i;
        if (gm >= M) continue;
#pragma unroll
        for (int j = 0; j < 8; j++) {
            int gn = n0 + tx * 8 + j;
            if (gn >= N) continue;
            float v = acc[i][j];
            if (HB) v += bias[gn];
            if (SP) v = softplusf(v);
            C[(size_t)gm * N + gn] = v;
        }
    }
}

// ---------------- mean / logvar heads ---------------------------------------
__global__ void meanlogvar_kernel(const float* __restrict__ en2,
                                  const float* __restrict__ mW, const float* __restrict__ mb,
                                  const float* __restrict__ lW, const float* __restrict__ lb,
                                  float* __restrict__ pm, float* __restrict__ lv)
{
    int t = blockIdx.x * blockDim.x + threadIdx.x;
    if (t >= NB * 4) return;
    int n = t >> 2, j = t & 3;
    const float* w = (j < 2) ? (mW + j * E2) : (lW + (j - 2) * E2);
    const float* x = en2 + (size_t)n * E2;
    float s = 0.f;
    for (int i = 0; i < E2; i += 4) {
        float4 xa = *reinterpret_cast<const float4*>(x + i);
        float4 wa = *reinterpret_cast<const float4*>(w + i);
        s += xa.x * wa.x + xa.y * wa.y + xa.z * wa.z + xa.w * wa.w;
    }
    if (j < 2) pm[n * 2 + j] = s + mb[j];
    else       lv[n * 2 + (j - 2)] = s + lb[j - 2];
}

// ---------------- column stats of (R x 2) -----------------------------------
__global__ void colstats_kernel(const float* __restrict__ X, int R, float* __restrict__ out)
{
    __shared__ float ss[256], s2[256];
    int c = blockIdx.x, tid = threadIdx.x;
    float s = 0.f, q = 0.f;
    for (int r = tid; r < R; r += 256) {
        float x = X[r * 2 + c];
        s += x; q += x * x;
    }
    ss[tid] = s; s2[tid] = q;
    __syncthreads();
    for (int st = 128; st > 0; st >>= 1) {
        if (tid < st) { ss[tid] += ss[tid + st]; s2[tid] += s2[tid + st]; }
        __syncthreads();
    }
    if (tid == 0) {
        float m = ss[0] / R;
        out[c] = m;
        out[2 + c] = s2[0] / R - m * m;
    }
}

// ---------------- z ----------------------------------------------------------
__global__ void z_kernel(const float* __restrict__ pm, const float* __restrict__ lv,
                         const float* __restrict__ spm, const float* __restrict__ slv,
                         const float* __restrict__ gm, const float* __restrict__ bm,
                         const float* __restrict__ gl, const float* __restrict__ bl,
                         const float* __restrict__ eps,
                         float* __restrict__ gz, float* __restrict__ outz)
{
    int idx = blockIdx.x * 256 + threadIdx.x;
    if (idx >= NB * CC) return;
    int c = idx & 1;
    float pmb = gm[c] * (pm[idx] - spm[c]) * rsqrtf(spm[2 + c] + 1e-5f) + bm[c];
    float lvb = gl[c] * (lv[idx] - slv[c]) * rsqrtf(slv[2 + c] + 1e-5f) + bl[c];
    float z = pmb + sqrtf(expf(lvb)) * eps[idx];
    gz[idx] = z;
    outz[idx] = z;
}

// ---------------- BN apply ---------------------------------------------------
__global__ void bn_apply_kernel(const float* __restrict__ X, const float* __restrict__ stats,
                                const float* __restrict__ g, const float* __restrict__ b,
                                int total, float* __restrict__ o1, float* __restrict__ o2)
{
    int idx = blockIdx.x * 256 + threadIdx.x;
    if (idx >= total) return;
    int c = idx & 1;
    float y = g[c] * (X[idx] - stats[c]) * rsqrtf(stats[2 + c] + 1e-5f) + b[c];
    o1[idx] = y;
    o2[idx] = y;
}

// ---------------- theta ------------------------------------------------------
__global__ void theta_kernel(const float* __restrict__ zx, const float* __restrict__ zc,
                             float* __restrict__ gtheta, float* __restrict__ otheta)
{
    __shared__ float sz[KK * 2];
    __shared__ float red[256];
    int n = blockIdx.x, tid = threadIdx.x;
    for (int i = tid; i < KK * 2; i += 256) sz[i] = zc[i];
    __syncthreads();
    float x0 = zx[n * 2], x1 = zx[n * 2 + 1];
    float l = -FLT_MAX;
    if (tid < KK) {
        float dx = x0 - sz[tid * 2];
        float dy = x1 - sz[tid * 2 + 1];
        l = -0.5f * (dx * dx + dy * dy);
    }
    red[tid] = l;
    __syncthreads();
    for (int st = 128; st > 0; st >>= 1) {
        if (tid < st) red[tid] = fmaxf(red[tid], red[tid + st]);
        __syncthreads();
    }
    float mx = red[0];
    __syncthreads();
    float e = (tid < KK) ? expf(l - mx) : 0.f;
    red[tid] = e;
    __syncthreads();
    for (int st = 128; st > 0; st >>= 1) {
        if (tid < st) red[tid] += red[tid + st];
        __syncthreads();
    }
    float inv = 1.f / red[0];
    if (tid < KK) {
        float th = e * inv;
        gtheta[(size_t)n * KK + tid] = th;
        otheta[(size_t)n * KK + tid] = th;
    }
}

// ---------------- decoder MLP ------------------------------------------------
__global__ void mu1_kernel(const float* __restrict__ zc, const float* __restrict__ W,
                           const float* __restrict__ b, float* __restrict__ out)
{
    int t = blockIdx.x * 256 + threadIdx.x;
    if (t >= KK * 100) return;
    int k = t / 100, j = t % 100;
    float v = zc[k * 2] * W[j * 2] + zc[k * 2 + 1] * W[j * 2 + 1] + b[j];
    out[t] = softplusf(v);
}

__global__ void mu2_kernel(const float* __restrict__ mu1, const float* __restrict__ W,
                           const float* __restrict__ b, float* __restrict__ out)
{
    __shared__ float row[100];
    int k = blockIdx.x, tid = threadIdx.x;
    if (tid < 100) row[tid] = mu1[k * 100 + tid];
    __syncthreads();
    if (tid < 100) {
        const float* w = W + tid * 100;
        float s = b[tid];
        for (int i = 0; i < 100; i++) s += row[i] * w[i];
        out[k * 100 + tid] = softplusf(s);
    }
}

__global__ void muz_kernel(const float* __restrict__ mu2, const float* __restrict__ W,
                           const float* __restrict__ b, float* __restrict__ out)
{
    __shared__ float row[100];
    int k = blockIdx.x, tid = threadIdx.x;
    if (tid < 100) row[tid] = mu2[k * 100 + tid];
    __syncthreads();
    for (int j = tid; j < EMB; j += 128) {
        const float* w = W + j * 100;
        float s = b[j];
        for (int i = 0; i < 100; i++) s += row[i] * w[i];
        out[k * EMB + j] = s;
    }
}

// ---------------- beta -------------------------------------------------------
__global__ void __launch_bounds__(1024)
beta_kernel(const float* __restrict__ logits, const float* __restrict__ bbias,
            const float* __restrict__ gdec, const float* __restrict__ bdec,
            float* __restrict__ beta)
{
    __shared__ float red[1024];
    __shared__ float red2[1024];
    const int k = blockIdx.x, tid = threadIdx.x;
    const float* row = logits + (size_t)k * VV;
    const float* bb  = bbias + (size_t)k * VV;

    float s = 0.f, q = 0.f;
    for (int v = tid; v < VV; v += 1024) { float x = row[v]; s += x; q += x * x; }
    red[tid] = s; red2[tid] = q;
    __syncthreads();
    for (int st = 512; st > 0; st >>= 1) {
        if (tid < st) { red[tid] += red[tid + st]; red2[tid] += red2[tid + st]; }
        __syncthreads();
    }
    float mean = red[0] / VV;
    float var  = red2[0] / VV - mean * mean;
    float scale = gdec[k] * rsqrtf(var + 1e-5f);
    float shift = bdec[k] - mean * scale;
    __syncthreads();

    float mx = -FLT_MAX;
    for (int v = tid; v < VV; v += 1024) {
        float y = row[v] * scale + shift + bb[v];
        mx = fmaxf(mx, y);
    }
    red[tid] = mx;
    __syncthreads();
    for (int st = 512; st > 0; st >>= 1) {
        if (tid < st) red[tid] = fmaxf(red[tid], red[tid + st]);
        __syncthreads();
    }
    mx = red[0];
    __syncthreads();

    float se = 0.f;
    for (int v = tid; v < VV; v += 1024) {
        float y = row[v] * scale + shift + bb[v];
        se += expf(y - mx);
    }
    red[tid] = se;
    __syncthreads();
    for (int st = 512; st > 0; st >>= 1) {
        if (tid < st) red[tid] += red[tid + st];
        __syncthreads();
    }
    float inv = 1.f / red[0];

    for (int v = tid; v < VV; v += 1024) {
        float y = row[v] * scale + shift + bb[v];
        beta[(size_t)k * VV + v] = expf(y - mx) * inv;
    }
}

// ---------------- launch -----------------------------------------------------
extern "C" void kernel_launch(void* const* d_in, const int* in_sizes, int n_in,
                              void* d_out, int out_size)
{
    const float* input_   = (const float*)d_in[0];
    const float* eps      = (const float*)d_in[2];
    const float* en1_W    = (const float*)d_in[3];
    const float* en1_b    = (const float*)d_in[4];
    const float* en2_W    = (const float*)d_in[5];
    const float* en2_b    = (const float*)d_in[6];
    const float* mean_W   = (const float*)d_in[7];
    const float* mean_b   = (const float*)d_in[8];
    const float* logvar_W = (const float*)d_in[9];
    const float* logvar_b = (const float*)d_in[10];
    const float* mu1_W    = (const float*)d_in[11];
    const float* mu1_b    = (const float*)d_in[12];
    const float* mu2_W    = (const float*)d_in[13];
    const float* mu2_b    = (const float*)d_in[14];
    const float* mu_W     = (const float*)d_in[15];
    const float* mu_b     = (const float*)d_in[16];
    const float* topics   = (const float*)d_in[17];
    const float* bbias    = (const float*)d_in[18];
    const float* emb      = (const float*)d_in[19];
    const float* g_mean   = (const float*)d_in[20];
    const float* b_mean   = (const float*)d_in[21];
    const float* g_logvar = (const float*)d_in[22];
    const float* b_logvar = (const float*)d_in[23];
    const float* g_x      = (const float*)d_in[24];
    const float* b_x      = (const float*)d_in[25];
    const float* g_phi    = (const float*)d_in[26];
    const float* b_phi    = (const float*)d_in[27];
    const float* g_dec    = (const float*)d_in[28];
    const float* b_dec    = (const float*)d_in[29];

    float* out = (float*)d_out;
    float* out_z     = out;
    float* out_recon = out + (long long)NB * CC;
    float* out_zx    = out_recon + (long long)NB * VV;
    float* out_zc    = out_zx + (long long)NB * CC;
    float* out_theta = out_zc + (long long)KK * CC;

    void* sp = nullptr;
    cudaGetSymbolAddress(&sp, g_scratch);
    float* S = (float*)sp;
    float* s_en1    = S + OFF_EN1;
    float* s_en2    = S + OFF_EN2;
    float* s_pm     = S + OFF_PM;
    float* s_lv     = S + OFF_LV;
    float* s_z      = S + OFF_Z;
    float* s_zx     = S + OFF_ZX;
    float* s_zc     = S + OFF_ZC;
    float* s_theta  = S + OFF_THETA;
    float* s_mu1    = S + OFF_MU1;
    float* s_mu2    = S + OFF_MU2;
    float* s_muz    = S + OFF_MUZ;
    float* s_logits = S + OFF_LOGITS;
    float* s_beta   = S + OFF_BETA;
    float* st_pm    = S + OFF_SPM;
    float* st_lv    = S + OFF_SLV;
    float* st_z     = S + OFF_SZ;
    float* st_t     = S + OFF_ST;

    // 1) en1 = softplus(input @ en1_W^T + b)  — tensor cores, 3xTF32
    gemm1_tf32x3<<<dim3(E1 / 64, NB / 128), 256>>>(input_, en1_W, en1_b, s_en1);

    // 2) en2 = softplus(en1 @ en2_W^T + b)    — fp32 SIMT (cheap)
    gemm_nt_kernel<true, true><<<dim3(E2 / 128, NB / 128), 256>>>(
        s_en1, en2_W, en2_b, s_en2, NB, E2, E1);

    // 3) heads
    meanlogvar_kernel<<<(NB * 4 + 255) / 256, 256>>>(
        s_en2, mean_W, mean_b, logvar_W, logvar_b, s_pm, s_lv);

    // 4) BN stats + z
    colstats_kernel<<<2, 256>>>(s_pm, NB, st_pm);
    colstats_kernel<<<2, 256>>>(s_lv, NB, st_lv);
    z_kernel<<<(NB * CC + 255) / 256, 256>>>(
        s_pm, s_lv, st_pm, st_lv, g_mean, b_mean, g_logvar, b_logvar, eps, s_z, out_z);

    // 5) zx, zc
    colstats_kernel<<<2, 256>>>(s_z, NB, st_z);
    bn_apply_kernel<<<(NB * CC + 255) / 256, 256>>>(s_z, st_z, g_x, b_x, NB * CC, s_zx, out_zx);
    colstats_kernel<<<2, 256>>>(topics, KK, st_t);
    bn_apply_kernel<<<(KK * CC + 255) / 256, 256>>>(topics, st_t, g_phi, b_phi, KK * CC, s_zc, out_zc);

    // 6) theta
    theta_kernel<<<NB, 256>>>(s_zx, s_zc, s_theta, out_theta);

    // 7) decoder MLP
    mu1_kernel<<<(KK * 100 + 255) / 256, 256>>>(s_zc, mu1_W, mu1_b, s_mu1);
    mu2_kernel<<<KK, 128>>>(s_mu1, mu2_W, mu2_b, s_mu2);
    muz_kernel<<<KK, 128>>>(s_mu2, mu_W, mu_b, s_muz);

    // 8) logits = mu_z @ emb^T  — fp32 SIMT
    gemm_nt_kernel<false, false><<<dim3((VV + 127) / 128, (KK + 127) / 128), 256>>>(
        s_muz, emb, nullptr, s_logits, KK, VV, EMB);

    // 9) beta
    beta_kernel<<<KK, 1024>>>(s_logits, bbias, g_dec, b_dec, s_beta);

    // 10) recon = theta @ beta  — tensor cores, tf32
    recon_tf32<<<dim3((VV + 127) / 128, NB / 128), 256>>>(s_theta, s_beta, out_recon);

    (void)in_sizes; (void)n_in; (void)out_size;
}

// round 4
// speedup vs baseline: 4.1169x; 1.8310x over previous
#include <cuda_runtime.h>
#include <cuda_bf16.h>
#include <math.h>
#include <float.h>
#include <stdint.h>

// ---------------- problem dims ----------------
#define NB   2048
#define VV   50000
#define E1   1024
#define E2   512
#define CC   2
#define KK   200
#define EMB  300

// ---------------- scratch ----------------------------------------------------
#define OFF_EN1    0LL
#define OFF_EN2    (OFF_EN1 + (long long)NB*E1)
#define OFF_PM     (OFF_EN2 + (long long)NB*E2)
#define OFF_LV     (OFF_PM + (long long)NB*CC)
#define OFF_Z      (OFF_LV + (long long)NB*CC)
#define OFF_ZX     (OFF_Z + (long long)NB*CC)
#define OFF_ZC     (OFF_ZX + (long long)NB*CC)
#define OFF_THETA  (OFF_ZC + (long long)KK*CC)
#define OFF_MU1    (OFF_THETA + (long long)NB*KK)
#define OFF_MU2    (OFF_MU1 + (long long)KK*100)
#define OFF_MUZ    (OFF_MU2 + (long long)KK*100)
#define OFF_LOGITS (OFF_MUZ + (long long)KK*EMB)
#define OFF_BETA   (OFF_LOGITS + (long long)KK*VV)
#define OFF_SPM    (OFF_BETA + (long long)KK*VV)
#define OFF_SLV    (OFF_SPM + 4)
#define OFF_SZ     (OFF_SLV + 4)
#define OFF_ST     (OFF_SZ + 4)
#define SCRATCH_FLOATS (OFF_ST + 8)

__device__ float g_scratch[SCRATCH_FLOATS];

__device__ __forceinline__ float softplusf(float x) {
    return fmaxf(x, 0.0f) + log1pf(expf(-fabsf(x)));
}

// pack two floats into bf16x2 (lo = first arg, hi = second)
__device__ __forceinline__ uint32_t pk_bf16(float lo, float hi) {
    uint32_t r;
    asm("cvt.rn.bf16x2.f32 %0, %1, %2;" : "=r"(r) : "f"(hi), "f"(lo));
    return r;
}

__device__ __forceinline__ void mma_bf16(float* d,
                                         uint32_t a0, uint32_t a1, uint32_t a2, uint32_t a3,
                                         uint32_t b0, uint32_t b1)
{
    asm volatile(
        "mma.sync.aligned.m16n8k16.row.col.f32.bf16.bf16.f32 "
        "{%0,%1,%2,%3},{%4,%5,%6,%7},{%8,%9},{%0,%1,%2,%3};"
        : "+f"(d[0]), "+f"(d[1]), "+f"(d[2]), "+f"(d[3])
        : "r"(a0), "r"(a1), "r"(a2), "r"(a3), "r"(b0), "r"(b1));
}

// =============================================================================
// NT GEMM, 3xBF16 split (hh + hl + lh): C = act(A[M,K] @ B[N,K]^T + bias)
// Block 128x128, BK=32, 512 threads (16 warps, warp tile 32x32), double buffer.
// SMEM words per buffer: Ah[128][20] @0, Al @2560, Bh @5120, Bl @7680 (stride
// 20 words/row = conflict-free for frag loads). Two buffers, 81920 bytes.
// =============================================================================
#define NTB_SMEM (2 * 10240 * 4)

template<bool SP, bool HB, bool CHKMN>
__global__ void __launch_bounds__(512, 1)
gemm_nt_bf16x3(const float* __restrict__ A, const float* __restrict__ B,
               const float* __restrict__ bias, float* __restrict__ C,
               int M, int N, int K)
{
    extern __shared__ __align__(16) uint32_t sw[];
    const int tid = threadIdx.x;
    const int lane = tid & 31, warp = tid >> 5;
    const int gid = lane >> 2, tig = lane & 3;
    const int wm = warp >> 2, wn = warp & 3;
    const int m0 = blockIdx.y * 128, n0 = blockIdx.x * 128;
    const int nt = (K + 31) / 32;

    float acc[2][4][4];
#pragma unroll
    for (int i = 0; i < 2; i++)
#pragma unroll
        for (int j = 0; j < 4; j++)
#pragma unroll
            for (int l = 0; l < 4; l++) acc[i][j][l] = 0.0f;

    const int srow = tid >> 3;          // staging row 0..63 (x2 via l)
    const int sq   = tid & 7;           // float4 index within 32-wide row

    float4 stA[2], stB[2];

    auto load_tile = [&](int t) {
        const int k0 = t * 32;
        const int gk = k0 + sq * 4;
#pragma unroll
        for (int l = 0; l < 2; l++) {
            int row = srow + l * 64;
            // ---- A ----
            {
                int gm = m0 + row;
                float4 v = make_float4(0.f, 0.f, 0.f, 0.f);
                bool rok = (!CHKMN) || (gm < M);
                if (rok) {
                    if (gk + 3 < K) {
                        v = *reinterpret_cast<const float4*>(A + (size_t)gm * K + gk);
                    } else if (gk < K) {
                        const float* p = A + (size_t)gm * K;
                        v.x = p[gk];
                        if (gk + 1 < K) v.y = p[gk + 1];
                        if (gk + 2 < K) v.z = p[gk + 2];
                        if (gk + 3 < K) v.w = p[gk + 3];
                    }
                }
                stA[l] = v;
            }
            // ---- B ----
            {
                int gn = n0 + row;
                float4 v = make_float4(0.f, 0.f, 0.f, 0.f);
                bool rok = (!CHKMN) || (gn < N);
                if (rok) {
                    if (gk + 3 < K) {
                        v = *reinterpret_cast<const float4*>(B + (size_t)gn * K + gk);
                    } else if (gk < K) {
                        const float* p = B + (size_t)gn * K;
                        v.x = p[gk];
                        if (gk + 1 < K) v.y = p[gk + 1];
                        if (gk + 2 < K) v.z = p[gk + 2];
                        if (gk + 3 < K) v.w = p[gk + 3];
                    }
                }
                stB[l] = v;
            }
        }
    };

    auto store_tile = [&](uint32_t* buf) {
#pragma unroll
        for (int l = 0; l < 2; l++) {
            int row = srow + l * 64;
            uint32_t w = (uint32_t)(row * 20 + sq * 2);
            // A
            {
                float4 v = stA[l];
                __nv_bfloat16 hx = __float2bfloat16_rn(v.x);
                __nv_bfloat16 hy = __float2bfloat16_rn(v.y);
                __nv_bfloat16 hz = __float2bfloat16_rn(v.z);
                __nv_bfloat16 hw = __float2bfloat16_rn(v.w);
                buf[w]     = ((uint32_t)__bfloat16_as_ushort(hy) << 16) | __bfloat16_as_ushort(hx);
                buf[w + 1] = ((uint32_t)__bfloat16_as_ushort(hw) << 16) | __bfloat16_as_ushort(hz);
                buf[w + 2560]     = pk_bf16(v.x - __bfloat162float(hx), v.y - __bfloat162float(hy));
                buf[w + 2560 + 1] = pk_bf16(v.z - __bfloat162float(hz), v.w - __bfloat162float(hw));
            }
            // B
            {
                float4 v = stB[l];
                __nv_bfloat16 hx = __float2bfloat16_rn(v.x);
                __nv_bfloat16 hy = __float2bfloat16_rn(v.y);
                __nv_bfloat16 hz = __float2bfloat16_rn(v.z);
                __nv_bfloat16 hw = __float2bfloat16_rn(v.w);
                buf[w + 5120]     = ((uint32_t)__bfloat16_as_ushort(hy) << 16) | __bfloat16_as_ushort(hx);
                buf[w + 5120 + 1] = ((uint32_t)__bfloat16_as_ushort(hw) << 16) | __bfloat16_as_ushort(hz);
                buf[w + 7680]     = pk_bf16(v.x - __bfloat162float(hx), v.y - __bfloat162float(hy));
                buf[w + 7680 + 1] = pk_bf16(v.z - __bfloat162float(hz), v.w - __bfloat162float(hw));
            }
        }
    };

    // prologue
    load_tile(0);
    store_tile(sw);
    __syncthreads();

    for (int t = 0; t < nt; t++) {
        const int b = t & 1;
        uint32_t* bb = sw + b * 10240;

        if (t + 1 < nt) load_tile(t + 1);

        // compute two k16 steps from buffer b
#pragma unroll
        for (int kkw = 0; kkw < 16; kkw += 8) {
            uint32_t ah[2][4], al[2][4], bh[4][2], bl[4][2];
#pragma unroll
            for (int ms = 0; ms < 2; ms++) {
                int base = (wm * 32 + ms * 16 + gid) * 20 + kkw + tig;
                ah[ms][0] = bb[base];
                ah[ms][1] = bb[base + 160];
                ah[ms][2] = bb[base + 4];
                ah[ms][3] = bb[base + 164];
                al[ms][0] = bb[base + 2560];
                al[ms][1] = bb[base + 2560 + 160];
                al[ms][2] = bb[base + 2560 + 4];
                al[ms][3] = bb[base + 2560 + 164];
            }
#pragma unroll
            for (int ns = 0; ns < 4; ns++) {
                int base = 5120 + (wn * 32 + ns * 8 + gid) * 20 + kkw + tig;
                bh[ns][0] = bb[base];
                bh[ns][1] = bb[base + 4];
                bl[ns][0] = bb[base + 2560];
                bl[ns][1] = bb[base + 2560 + 4];
            }
#pragma unroll
            for (int ms = 0; ms < 2; ms++)
#pragma unroll
                for (int ns = 0; ns < 4; ns++) {
                    mma_bf16(acc[ms][ns], ah[ms][0], ah[ms][1], ah[ms][2], ah[ms][3],
                             bh[ns][0], bh[ns][1]);
                    mma_bf16(acc[ms][ns], ah[ms][0], ah[ms][1], ah[ms][2], ah[ms][3],
                             bl[ns][0], bl[ns][1]);
                    mma_bf16(acc[ms][ns], al[ms][0], al[ms][1], al[ms][2], al[ms][3],
                             bh[ns][0], bh[ns][1]);
                }
        }

        if (t + 1 < nt) store_tile(sw + (b ^ 1) * 10240);
        __syncthreads();
    }

    // epilogue
#pragma unroll
    for (int ms = 0; ms < 2; ms++) {
        int r0 = m0 + wm * 32 + ms * 16 + gid;
#pragma unroll
        for (int ns = 0; ns < 4; ns++) {
            int c0 = n0 + wn * 32 + ns * 8 + 2 * tig;
            float bv0 = 0.f, bv1 = 0.f;
            if (HB) {
                bv0 = bias[c0];
                bv1 = bias[c0 + 1];
            }
            float v00 = acc[ms][ns][0] + bv0;
            float v01 = acc[ms][ns][1] + bv1;
            float v10 = acc[ms][ns][2] + bv0;
            float v11 = acc[ms][ns][3] + bv1;
            if (SP) { v00 = softplusf(v00); v01 = softplusf(v01);
                      v10 = softplusf(v10); v11 = softplusf(v11); }
            if (!CHKMN) {
                C[(size_t)r0 * N + c0]           = v00;
                C[(size_t)r0 * N + c0 + 1]       = v01;
                C[(size_t)(r0 + 8) * N + c0]     = v10;
                C[(size_t)(r0 + 8) * N + c0 + 1] = v11;
            } else {
                if (r0 < M) {
                    if (c0 < N)     C[(size_t)r0 * N + c0]     = v00;
                    if (c0 + 1 < N) C[(size_t)r0 * N + c0 + 1] = v01;
                }
                if (r0 + 8 < M) {
                    if (c0 < N)     C[(size_t)(r0 + 8) * N + c0]     = v10;
                    if (c0 + 1 < N) C[(size_t)(r0 + 8) * N + c0 + 1] = v11;
                }
            }
        }
    }
}

// ============================ mma.sync tf32 (recon) ==========================
__device__ __forceinline__ unsigned tf32_rna(float x) {
    unsigned r;
    asm("cvt.rna.tf32.f32 %0, %1;" : "=r"(r) : "f"(x));
    return r;
}

__device__ __forceinline__ void mma_tf32(float* d,
                                         unsigned a0, unsigned a1, unsigned a2, unsigned a3,
                                         unsigned b0, unsigned b1)
{
    asm volatile(
        "mma.sync.aligned.m16n8k8.row.col.f32.tf32.tf32.f32 "
        "{%0,%1,%2,%3},{%4,%5,%6,%7},{%8,%9},{%0,%1,%2,%3};"
        : "+f"(d[0]), "+f"(d[1]), "+f"(d[2]), "+f"(d[3])
        : "r"(a0), "r"(a1), "r"(a2), "r"(a3), "r"(b0), "r"(b1));
}

// =============================================================================
// recon = theta[2048,200] @ beta[200,50000]  (NN, single-pass tf32)
// =============================================================================
__global__ void __launch_bounds__(256, 2)
recon_tf32(const float* __restrict__ A, const float* __restrict__ B,
           float* __restrict__ C)
{
    __shared__ float Ah[128][20];
    __shared__ float Bh[16][136];
    const int tid = threadIdx.x;
    const int lane = tid & 31, warp = tid >> 5;
    const int gid = lane >> 2, tig = lane & 3;
    const int wm = warp >> 1, wn = warp & 1;
    const int m0 = blockIdx.y * 128;
    const int n0 = blockIdx.x * 128;

    float acc[2][8][4];
#pragma unroll
    for (int i = 0; i < 2; i++)
#pragma unroll
        for (int j = 0; j < 8; j++)
#pragma unroll
            for (int l = 0; l < 4; l++) acc[i][j][l] = 0.0f;

    for (int k0 = 0; k0 < KK; k0 += 16) {
#pragma unroll
        for (int l = 0; l < 2; l++) {
            int idx = tid + l * 256;
            int row = idx >> 2, kq = (idx & 3) * 4;
            int gk = k0 + kq;
            float4 v = make_float4(0.f, 0.f, 0.f, 0.f);
            if (gk + 3 < KK)
                v = *reinterpret_cast<const float4*>(A + (size_t)(m0 + row) * KK + gk);
            Ah[row][kq + 0] = __uint_as_float(tf32_rna(v.x));
            Ah[row][kq + 1] = __uint_as_float(tf32_rna(v.y));
            Ah[row][kq + 2] = __uint_as_float(tf32_rna(v.z));
            Ah[row][kq + 3] = __uint_as_float(tf32_rna(v.w));
        }
#pragma unroll
        for (int l = 0; l < 2; l++) {
            int idx = tid + l * 256;
            int kk = idx >> 5, nc = (idx & 31) * 4;
            int gk = k0 + kk, gn = n0 + nc;
            float4 v = make_float4(0.f, 0.f, 0.f, 0.f);
            if (gk < KK && gn + 3 < VV)
                v = *reinterpret_cast<const float4*>(B + (size_t)gk * VV + gn);
            Bh[kk][nc + 0] = __uint_as_float(tf32_rna(v.x));
            Bh[kk][nc + 1] = __uint_as_float(tf32_rna(v.y));
            Bh[kk][nc + 2] = __uint_as_float(tf32_rna(v.z));
            Bh[kk][nc + 3] = __uint_as_float(tf32_rna(v.w));
        }
        __syncthreads();

#pragma unroll
        for (int kk = 0; kk < 16; kk += 8) {
            unsigned a[2][4], b[8][2];
#pragma unroll
            for (int ms = 0; ms < 2; ms++) {
                int r = wm * 32 + ms * 16 + gid;
                a[ms][0] = __float_as_uint(Ah[r][kk + tig]);
                a[ms][1] = __float_as_uint(Ah[r + 8][kk + tig]);
                a[ms][2] = __float_as_uint(Ah[r][kk + tig + 4]);
                a[ms][3] = __float_as_uint(Ah[r + 8][kk + tig + 4]);
            }
#pragma unroll
            for (int ns = 0; ns < 8; ns++) {
                int n = wn * 64 + ns * 8 + gid;
                b[ns][0] = __float_as_uint(Bh[kk + tig][n]);
                b[ns][1] = __float_as_uint(Bh[kk + tig + 4][n]);
            }
#pragma unroll
            for (int ms = 0; ms < 2; ms++)
#pragma unroll
                for (int ns = 0; ns < 8; ns++)
                    mma_tf32(acc[ms][ns], a[ms][0], a[ms][1], a[ms][2], a[ms][3],
                             b[ns][0], b[ns][1]);
        }
        __syncthreads();
    }

#pragma unroll
    for (int ms = 0; ms < 2; ms++) {
        int r0 = m0 + wm * 32 + ms * 16 + gid;
#pragma unroll
        for (int ns = 0; ns < 8; ns++) {
            int c0 = n0 + wn * 64 + ns * 8 + 2 * tig;
            if (c0 < VV) {
                C[(size_t)r0 * VV + c0]       = acc[ms][ns][0];
                C[(size_t)(r0 + 8) * VV + c0] = acc[ms][ns][2];
            }
            if (c0 + 1 < VV) {
                C[(size_t)r0 * VV + c0 + 1]       = acc[ms][ns][1];
                C[(size_t)(r0 + 8) * VV + c0 + 1] = acc[ms][ns][3];
            }
        }
    }
}

// ---------------- fp32 NT GEMM (GEMM2) ---------------------------------------
template<bool SP, bool HB>
__global__ void __launch_bounds__(256)
gemm_nt_kernel(const float* __restrict__ A, const float* __restrict__ B,
               const float* __restrict__ bias, float* __restrict__ C,
               int M, int N, int K)
{
    __shared__ float As[16][132];
    __shared__ float Bs[16][132];
    const int tid = threadIdx.x;
    const int m0 = blockIdx.y * 128;
    const int n0 = blockIdx.x * 128;
    const int tx = tid & 15;
    const int ty = tid >> 4;

    float acc[8][8];
#pragma unroll
    for (int i = 0; i < 8; i++)
#pragma unroll
        for (int j = 0; j < 8; j++) acc[i][j] = 0.0f;

    for (int k0 = 0; k0 < K; k0 += 16) {
#pragma unroll
        for (int l = 0; l < 2; l++) {
            int u   = tid + l * 256;
            int row = u >> 2;
            int kq  = (u & 3) * 4;
            int gk  = k0 + kq;
            {
                int gm = m0 + row;
                float4 v = make_float4(0.f, 0.f, 0.f, 0.f);
                if (gm < M && gk + 3 < K)
                    v = *reinterpret_cast<const float4*>(A + (size_t)gm * K + gk);
                As[kq + 0][row] = v.x; As[kq + 1][row] = v.y;
                As[kq + 2][row] = v.z; As[kq + 3][row] = v.w;
            }
            {
                int gn = n0 + row;
                float4 v = make_float4(0.f, 0.f, 0.f, 0.f);
                if (gn < N && gk + 3 < K)
                    v = *reinterpret_cast<const float4*>(B + (size_t)gn * K + gk);
                Bs[kq + 0][row] = v.x; Bs[kq + 1][row] = v.y;
                Bs[kq + 2][row] = v.z; Bs[kq + 3][row] = v.w;
            }
        }
        __syncthreads();
#pragma unroll
        for (int kk = 0; kk < 16; kk++) {
            float a[8], b[8];
            *reinterpret_cast<float4*>(&a[0]) = *reinterpret_cast<const float4*>(&As[kk][ty * 8]);
            *reinterpret_cast<float4*>(&a[4]) = *reinterpret_cast<const float4*>(&As[kk][ty * 8 + 4]);
            *reinterpret_cast<float4*>(&b[0]) = *reinterpret_cast<const float4*>(&Bs[kk][tx * 8]);
            *reinterpret_cast<float4*>(&b[4]) = *reinterpret_cast<const float4*>(&Bs[kk][tx * 8 + 4]);
#pragma unroll
            for (int i = 0; i < 8; i++)
#pragma unroll
                for (int j = 0; j < 8; j++)
                    acc[i][j] += a[i] * b[j];
        }
        __syncthreads();
    }

#pragma unroll
    for (int i = 0; i < 8; i++) {
        int gm = m0 + ty * 8 + i;
        if (gm >= M) continue;
#pragma unroll
        for (int j = 0; j < 8; j++) {
            int gn = n0 + tx * 8 + j;
            if (gn >= N) continue;
            float v = acc[i][j];
            if (HB) v += bias[gn];
            if (SP) v = softplusf(v);
            C[(size_t)gm * N + gn] = v;
        }
    }
}

// ---------------- mean / logvar heads ---------------------------------------
__global__ void meanlogvar_kernel(const float* __restrict__ en2,
                                  const float* __restrict__ mW, const float* __restrict__ mb,
                                  const float* __restrict__ lW, const float* __restrict__ lb,
                                  float* __restrict__ pm, float* __restrict__ lv)
{
    int t = blockIdx.x * blockDim.x + threadIdx.x;
    if (t >= NB * 4) return;
    int n = t >> 2, j = t & 3;
    const float* w = (j < 2) ? (mW + j * E2) : (lW + (j - 2) * E2);
    const float* x = en2 + (size_t)n * E2;
    float s = 0.f;
    for (int i = 0; i < E2; i += 4) {
        float4 xa = *reinterpret_cast<const float4*>(x + i);
        float4 wa = *reinterpret_cast<const float4*>(w + i);
        s += xa.x * wa.x + xa.y * wa.y + xa.z * wa.z + xa.w * wa.w;
    }
    if (j < 2) pm[n * 2 + j] = s + mb[j];
    else       lv[n * 2 + (j - 2)] = s + lb[j - 2];
}

// ---------------- column stats of (R x 2) -----------------------------------
__global__ void colstats_kernel(const float* __restrict__ X, int R, float* __restrict__ out)
{
    __shared__ float ss[256], s2[256];
    int c = blockIdx.x, tid = threadIdx.x;
    float s = 0.f, q = 0.f;
    for (int r = tid; r < R; r += 256) {
        float x = X[r * 2 + c];
        s += x; q += x * x;
    }
    ss[tid] = s; s2[tid] = q;
    __syncthreads();
    for (int st = 128; st > 0; st >>= 1) {
        if (tid < st) { ss[tid] += ss[tid + st]; s2[tid] += s2[tid + st]; }
        __syncthreads();
    }
    if (tid == 0) {
        float m = ss[0] / R;
        out[c] = m;
        out[2 + c] = s2[0] / R - m * m;
    }
}

// ---------------- z ----------------------------------------------------------
__global__ void z_kernel(const float* __restrict__ pm, const float* __restrict__ lv,
                         const float* __restrict__ spm, const float* __restrict__ slv,
                         const float* __restrict__ gm, const float* __restrict__ bm,
                         const float* __restrict__ gl, const float* __restrict__ bl,
                         const float* __restrict__ eps,
                         float* __restrict__ gz, float* __restrict__ outz)
{
    int idx = blockIdx.x * 256 + threadIdx.x;
    if (idx >= NB * CC) return;
    int c = idx & 1;
    float pmb = gm[c] * (pm[idx] - spm[c]) * rsqrtf(spm[2 + c] + 1e-5f) + bm[c];
    float lvb = gl[c] * (lv[idx] - slv[c]) * rsqrtf(slv[2 + c] + 1e-5f) + bl[c];
    float z = pmb + sqrtf(expf(lvb)) * eps[idx];
    gz[idx] = z;
    outz[idx] = z;
}

// ---------------- BN apply ---------------------------------------------------
__global__ void bn_apply_kernel(const float* __restrict__ X, const float* __restrict__ stats,
                                const float* __restrict__ g, const float* __restrict__ b,
                                int total, float* __restrict__ o1, float* __restrict__ o2)
{
    int idx = blockIdx.x * 256 + threadIdx.x;
    if (idx >= total) return;
    int c = idx & 1;
    float y = g[c] * (X[idx] - stats[c]) * rsqrtf(stats[2 + c] + 1e-5f) + b[c];
    o1[idx] = y;
    o2[idx] = y;
}

// ---------------- theta ------------------------------------------------------
__global__ void theta_kernel(const float* __restrict__ zx, const float* __restrict__ zc,
                             float* __restrict__ gtheta, float* __restrict__ otheta)
{
    __shared__ float sz[KK * 2];
    __shared__ float red[256];
    int n = blockIdx.x, tid = threadIdx.x;
    for (int i = tid; i < KK * 2; i += 256) sz[i] = zc[i];
    __syncthreads();
    float x0 = zx[n * 2], x1 = zx[n * 2 + 1];
    float l = -FLT_MAX;
    if (tid < KK) {
        float dx = x0 - sz[tid * 2];
        float dy = x1 - sz[tid * 2 + 1];
        l = -0.5f * (dx * dx + dy * dy);
    }
    red[tid] = l;
    __syncthreads();
    for (int st = 128; st > 0; st >>= 1) {
        if (tid < st) red[tid] = fmaxf(red[tid], red[tid + st]);
        __syncthreads();
    }
    float mx = red[0];
    __syncthreads();
    float e = (tid < KK) ? expf(l - mx) : 0.f;
    red[tid] = e;
    __syncthreads();
    for (int st = 128; st > 0; st >>= 1) {
        if (tid < st) red[tid] += red[tid + st];
        __syncthreads();
    }
    float inv = 1.f / red[0];
    if (tid < KK) {
        float th = e * inv;
        gtheta[(size_t)n * KK + tid] = th;
        otheta[(size_t)n * KK + tid] = th;
    }
}

// ---------------- decoder MLP ------------------------------------------------
__global__ void mu1_kernel(const float* __restrict__ zc, const float* __restrict__ W,
                           const float* __restrict__ b, float* __restrict__ out)
{
    int t = blockIdx.x * 256 + threadIdx.x;
    if (t >= KK * 100) return;
    int k = t / 100, j = t % 100;
    float v = zc[k * 2] * W[j * 2] + zc[k * 2 + 1] * W[j * 2 + 1] + b[j];
    out[t] = softplusf(v);
}

__global__ void mu2_kernel(const float* __restrict__ mu1, const float* __restrict__ W,
                           const float* __restrict__ b, float* __restrict__ out)
{
    __shared__ float row[100];
    int k = blockIdx.x, tid = threadIdx.x;
    if (tid < 100) row[tid] = mu1[k * 100 + tid];
    __syncthreads();
    if (tid < 100) {
        const float* w = W + tid * 100;
        float s = b[tid];
        for (int i = 0; i < 100; i++) s += row[i] * w[i];
        out[k * 100 + tid] = softplusf(s);
    }
}

__global__ void muz_kernel(const float* __restrict__ mu2, const float* __restrict__ W,
                           const float* __restrict__ b, float* __restrict__ out)
{
    __shared__ float row[100];
    int k = blockIdx.x, tid = threadIdx.x;
    if (tid < 100) row[tid] = mu2[k * 100 + tid];
    __syncthreads();
    for (int j = tid; j < EMB; j += 128) {
        const float* w = W + j * 100;
        float s = b[j];
        for (int i = 0; i < 100; i++) s += row[i] * w[i];
        out[k * EMB + j] = s;
    }
}

// ---------------- beta -------------------------------------------------------
__global__ void __launch_bounds__(1024)
beta_kernel(const float* __restrict__ logits, const float* __restrict__ bbias,
            const float* __restrict__ gdec, const float* __restrict__ bdec,
            float* __restrict__ beta)
{
    __shared__ float red[1024];
    __shared__ float red2[1024];
    const int k = blockIdx.x, tid = threadIdx.x;
    const float* row = logits + (size_t)k * VV;
    const float* bb  = bbias + (size_t)k * VV;

    float s = 0.f, q = 0.f;
    for (int v = tid; v < VV; v += 1024) { float x = row[v]; s += x; q += x * x; }
    red[tid] = s; red2[tid] = q;
    __syncthreads();
    for (int st = 512; st > 0; st >>= 1) {
        if (tid < st) { red[tid] += red[tid + st]; red2[tid] += red2[tid + st]; }
        __syncthreads();
    }
    float mean = red[0] / VV;
    float var  = red2[0] / VV - mean * mean;
    float scale = gdec[k] * rsqrtf(var + 1e-5f);
    float shift = bdec[k] - mean * scale;
    __syncthreads();

    float mx = -FLT_MAX;
    for (int v = tid; v < VV; v += 1024) {
        float y = row[v] * scale + shift + bb[v];
        mx = fmaxf(mx, y);
    }
    red[tid] = mx;
    __syncthreads();
    for (int st = 512; st > 0; st >>= 1) {
        if (tid < st) red[tid] = fmaxf(red[tid], red[tid + st]);
        __syncthreads();
    }
    mx = red[0];
    __syncthreads();

    float se = 0.f;
    for (int v = tid; v < VV; v += 1024) {
        float y = row[v] * scale + shift + bb[v];
        se += expf(y - mx);
    }
    red[tid] = se;
    __syncthreads();
    for (int st = 512; st > 0; st >>= 1) {
        if (tid < st) red[tid] += red[tid + st];
        __syncthreads();
    }
    float inv = 1.f / red[0];

    for (int v = tid; v < VV; v += 1024) {
        float y = row[v] * scale + shift + bb[v];
        beta[(size_t)k * VV + v] = expf(y - mx) * inv;
    }
}

// ---------------- launch -----------------------------------------------------
extern "C" void kernel_launch(void* const* d_in, const int* in_sizes, int n_in,
                              void* d_out, int out_size)
{
    const float* input_   = (const float*)d_in[0];
    const float* eps      = (const float*)d_in[2];
    const float* en1_W    = (const float*)d_in[3];
    const float* en1_b    = (const float*)d_in[4];
    const float* en2_W    = (const float*)d_in[5];
    const float* en2_b    = (const float*)d_in[6];
    const float* mean_W   = (const float*)d_in[7];
    const float* mean_b   = (const float*)d_in[8];
    const float* logvar_W = (const float*)d_in[9];
    const float* logvar_b = (const float*)d_in[10];
    const float* mu1_W    = (const float*)d_in[11];
    const float* mu1_b    = (const float*)d_in[12];
    const float* mu2_W    = (const float*)d_in[13];
    const float* mu2_b    = (const float*)d_in[14];
    const float* mu_W     = (const float*)d_in[15];
    const float* mu_b     = (const float*)d_in[16];
    const float* topics   = (const float*)d_in[17];
    const float* bbias    = (const float*)d_in[18];
    const float* emb      = (const float*)d_in[19];
    const float* g_mean   = (const float*)d_in[20];
    const float* b_mean   = (const float*)d_in[21];
    const float* g_logvar = (const float*)d_in[22];
    const float* b_logvar = (const float*)d_in[23];
    const float* g_x      = (const float*)d_in[24];
    const float* b_x      = (const float*)d_in[25];
    const float* g_phi    = (const float*)d_in[26];
    const float* b_phi    = (const float*)d_in[27];
    const float* g_dec    = (const float*)d_in[28];
    const float* b_dec    = (const float*)d_in[29];

    float* out = (float*)d_out;
    float* out_z     = out;
    float* out_recon = out + (long long)NB * CC;
    float* out_zx    = out_recon + (long long)NB * VV;
    float* out_zc    = out_zx + (long long)NB * CC;
    float* out_theta = out_zc + (long long)KK * CC;

    void* sp = nullptr;
    cudaGetSymbolAddress(&sp, g_scratch);
    float* S = (float*)sp;
    float* s_en1    = S + OFF_EN1;
    float* s_en2    = S + OFF_EN2;
    float* s_pm     = S + OFF_PM;
    float* s_lv     = S + OFF_LV;
    float* s_z      = S + OFF_Z;
    float* s_zx     = S + OFF_ZX;
    float* s_zc     = S + OFF_ZC;
    float* s_theta  = S + OFF_THETA;
    float* s_mu1    = S + OFF_MU1;
    float* s_mu2    = S + OFF_MU2;
    float* s_muz    = S + OFF_MUZ;
    float* s_logits = S + OFF_LOGITS;
    float* s_beta   = S + OFF_BETA;
    float* st_pm    = S + OFF_SPM;
    float* st_lv    = S + OFF_SLV;
    float* st_z     = S + OFF_SZ;
    float* st_t     = S + OFF_ST;

    cudaFuncSetAttribute(gemm_nt_bf16x3<true, true, false>,
                         cudaFuncAttributeMaxDynamicSharedMemorySize, NTB_SMEM);
    cudaFuncSetAttribute(gemm_nt_bf16x3<false, false, true>,
                         cudaFuncAttributeMaxDynamicSharedMemorySize, NTB_SMEM);

    // --- decoder side first (independent of encoder); gemm1 = launch #5 ---
    colstats_kernel<<<2, 256>>>(topics, KK, st_t);
    bn_apply_kernel<<<(KK * CC + 255) / 256, 256>>>(topics, st_t, g_phi, b_phi, KK * CC, s_zc, out_zc);
    mu1_kernel<<<(KK * 100 + 255) / 256, 256>>>(s_zc, mu1_W, mu1_b, s_mu1);
    mu2_kernel<<<KK, 128>>>(s_mu1, mu2_W, mu2_b, s_mu2);
    muz_kernel<<<KK, 128>>>(s_mu2, mu_W, mu_b, s_muz);

    // 5) en1 = softplus(input @ en1_W^T + b) — bf16x3 tensor cores
    gemm_nt_bf16x3<true, true, false><<<dim3(E1 / 128, NB / 128), 512, NTB_SMEM>>>(
        input_, en1_W, en1_b, s_en1, NB, E1, VV);

    // 6) en2
    gemm_nt_kernel<true, true><<<dim3(E2 / 128, NB / 128), 256>>>(
        s_en1, en2_W, en2_b, s_en2, NB, E2, E1);

    // 7) heads
    meanlogvar_kernel<<<(NB * 4 + 255) / 256, 256>>>(
        s_en2, mean_W, mean_b, logvar_W, logvar_b, s_pm, s_lv);

    // 8-10) BN stats + z
    colstats_kernel<<<2, 256>>>(s_pm, NB, st_pm);
    colstats_kernel<<<2, 256>>>(s_lv, NB, st_lv);
    z_kernel<<<(NB * CC + 255) / 256, 256>>>(
        s_pm, s_lv, st_pm, st_lv, g_mean, b_mean, g_logvar, b_logvar, eps, s_z, out_z);

    // 11-12) zx
    colstats_kernel<<<2, 256>>>(s_z, NB, st_z);
    bn_apply_kernel<<<(NB * CC + 255) / 256, 256>>>(s_z, st_z, g_x, b_x, NB * CC, s_zx, out_zx);

    // 13) theta
    theta_kernel<<<NB, 256>>>(s_zx, s_zc, s_theta, out_theta);

    // 14) logits = mu_z @ emb^T — bf16x3, bounds-checked
    gemm_nt_bf16x3<false, false, true><<<dim3((VV + 127) / 128, (KK + 127) / 128), 512, NTB_SMEM>>>(
        s_muz, emb, nullptr, s_logits, KK, VV, EMB);

    // 15) beta
    beta_kernel<<<KK, 1024>>>(s_logits, bbias, g_dec, b_dec, s_beta);

    // 16) recon = theta @ beta
    recon_tf32<<<dim3((VV + 127) / 128, NB / 128), 256>>>(s_theta, s_beta, out_recon);

    (void)in_sizes; (void)n_in; (void)out_size;
}